// round 1
// baseline (speedup 1.0000x reference)
#include <cuda_runtime.h>
#include <cuda_bf16.h>
#include <mma.h>

using namespace nvcuda;

// Problem constants
#define BB 128
#define SS 256
#define DD 512
#define HH 1024
#define NCC 128
#define NCTA_REC 128   // CTAs in persistent recurrent kernel (<=148 for co-residency)

// ---------------- device scratch (no cudaMalloc allowed) ----------------
__device__ float          g_P[(size_t)SS * BB * 4096];   // input-side gate preacts [s][b][g*1024+u], 512MB
__device__ __nv_bfloat16  g_h[BB * HH];                  // broadcast hidden state (bf16)
__device__ float          g_hf[BB * HH];                 // final hidden state (f32)
__device__ unsigned       g_cnt = 0;                     // grid barrier arrival counter
__device__ unsigned       g_gen = 0;                     // grid barrier generation (monotonic across replays)

__device__ __forceinline__ float sigm(float v) { return 1.0f / (1.0f + expf(-v)); }

// Sense-reversing grid barrier. Counter self-resets each use; generation is
// monotonic so graph replays work without any host-side reset.
__device__ __forceinline__ void gridbar()
{
    __syncthreads();
    if (threadIdx.x == 0) {
        __threadfence();
        volatile unsigned* gen = &g_gen;
        unsigned g0 = *gen;
        unsigned arr = atomicAdd(&g_cnt, 1u);
        if (arr == NCTA_REC - 1) {
            g_cnt = 0;
            __threadfence();
            *gen = g0 + 1u;
        } else {
            while (*gen == g0) { __nanosleep(40); }
        }
    }
    __syncthreads();
    __threadfence();   // acquire: subsequent global loads must see peers' h writes
}

// ======================================================================
// Kernel 1: input projections.  C[32768,4096] = gather(emb, x) @ [Wfx|Wix|Wgx|Wox] + bias
// Row m = s*128 + b; A row = emb[x[b][s]].  CTA tile 128x64, K=512, bf16 wmma.
// ======================================================================
__global__ __launch_bounds__(256) void k_input_proj(
    const int*   __restrict__ x,
    const float* __restrict__ emb,
    const float* __restrict__ Wfx, const float* __restrict__ bf,
    const float* __restrict__ Wix, const float* __restrict__ bi,
    const float* __restrict__ Wgx, const float* __restrict__ bg,
    const float* __restrict__ Wox, const float* __restrict__ bo)
{
    __shared__ __align__(32) __nv_bfloat16 As[128 * 16];  // [128][16]
    __shared__ __align__(32) __nv_bfloat16 Bs[16 * 64];   // [16][64]
    __shared__ __align__(32) float stage[8][16][64];      // 32KB epilogue staging
    __shared__ int rowidx[128];

    const int tn = blockIdx.x;         // 0..63  (64 cols each)
    const int tm = blockIdx.y;         // 0..255 (128 rows each)
    const int t  = threadIdx.x;
    const int w  = t >> 5;

    const int n0   = tn * 64;
    const int gate = n0 >> 10;
    const int h0   = n0 & 1023;
    const float* W    = (gate == 0) ? Wfx : (gate == 1) ? Wix : (gate == 2) ? Wgx : Wox;
    const float* bias = (gate == 0) ? bf  : (gate == 1) ? bi  : (gate == 2) ? bg  : bo;

    if (t < 128) {
        int m = tm * 128 + t;
        int s = m >> 7, b = m & 127;
        rowidx[t] = x[b * SS + s];
    }
    __syncthreads();

    wmma::fragment<wmma::accumulator, 16, 16, 16, float> acc[4];
#pragma unroll
    for (int i = 0; i < 4; i++) wmma::fill_fragment(acc[i], 0.0f);

    for (int kt = 0; kt < DD; kt += 16) {
        // A tile: 128x16 gathered from emb, converted to bf16
#pragma unroll
        for (int i = 0; i < 8; i++) {
            int e = t + i * 256;           // 0..2047
            int r = e >> 4, c = e & 15;
            As[r * 16 + c] = __float2bfloat16(emb[(size_t)rowidx[r] * DD + kt + c]);
        }
        // B tile: 16x64 from weight matrix
#pragma unroll
        for (int i = 0; i < 4; i++) {
            int e = t + i * 256;           // 0..1023
            int r = e >> 6, c = e & 63;
            Bs[r * 64 + c] = __float2bfloat16(W[(size_t)(kt + r) * HH + h0 + c]);
        }
        __syncthreads();

        wmma::fragment<wmma::matrix_a, 16, 16, 16, __nv_bfloat16, wmma::row_major> af;
        wmma::load_matrix_sync(af, As + (w * 16) * 16, 16);
#pragma unroll
        for (int nb = 0; nb < 4; nb++) {
            wmma::fragment<wmma::matrix_b, 16, 16, 16, __nv_bfloat16, wmma::row_major> bfg;
            wmma::load_matrix_sync(bfg, Bs + nb * 16, 64);
            wmma::mma_sync(acc[nb], af, bfg, acc[nb]);
        }
        __syncthreads();
    }

#pragma unroll
    for (int nb = 0; nb < 4; nb++)
        wmma::store_matrix_sync(&stage[w][0][nb * 16], acc[nb], 64, wmma::mem_row_major);
    __syncthreads();

#pragma unroll
    for (int i = 0; i < 32; i++) {
        int e = t + i * 256;               // 0..8191 = 128*64
        int r = e >> 6, c = e & 63;
        int m = tm * 128 + r;
        g_P[(size_t)m * 4096 + n0 + c] = stage[r >> 4][r & 15][c] + bias[h0 + c];
    }
}

// ======================================================================
// Kernel 2: persistent recurrent scan.  128 CTAs, each owns 8 hidden units
// (32 gate columns: col = gate*8 + j).  Weights cached in SMEM (bf16, col-major)
// for all 256 steps; C cached in SMEM; h broadcast via global bf16 + grid barrier.
// ======================================================================
__global__ void __launch_bounds__(256, 1) k_recur(
    const int*   __restrict__ x,
    const float* __restrict__ Wfh, const float* __restrict__ Wih,
    const float* __restrict__ Wgh, const float* __restrict__ Woh)
{
    extern __shared__ __align__(32) unsigned char dyn[];
    __nv_bfloat16* Ws = (__nv_bfloat16*)dyn;                  // [32 cols][1024 k] col-major: Ws[col*1024+k], 64KB
    float*         Sg = (float*)(dyn + 32 * 1024 * 2);        // [128][32] mma output staging, 16KB
    float*         Cs = Sg + 128 * 32;                        // [128][8] cell state, 4KB

    const int t  = threadIdx.x;
    const int w  = t >> 5;
    const int c  = blockIdx.x;
    const int u0 = c * 8;

    const float* Wg[4] = { Wfh, Wih, Wgh, Woh };

    // Load recurrent weight slice -> SMEM (coalesced over j within each (k,gate))
    for (int e = t; e < 32 * 1024; e += 256) {
        int k = e >> 5; int col = e & 31; int g = col >> 3; int j = col & 7;
        Ws[col * 1024 + k] = __float2bfloat16(Wg[g][(size_t)k * HH + u0 + j]);
    }
    // Zero own h slice and C
    for (int e = t; e < 1024; e += 256) {      // 128 b * 8 j
        int b = e >> 3, j = e & 7;
        g_h[b * HH + u0 + j] = __float2bfloat16(0.0f);
        Cs[b * 8 + j] = 0.0f;
    }
    gridbar();   // all h slices zeroed & visible

    for (int s = 0; s < SS; s++) {
        // ---- prefetch input-side preacts + reset mask (independent of h) ----
        float pf[4][4];
        int   xr[4];
#pragma unroll
        for (int i = 0; i < 4; i++) {
            int e = t + i * 256; int b = e >> 3, j = e & 7;
            const float* Pb = g_P + ((size_t)(s * BB + b)) * 4096 + (u0 + j);
            pf[i][0] = Pb[0];
            pf[i][1] = Pb[1024];
            pf[i][2] = Pb[2048];
            pf[i][3] = Pb[3072];
            xr[i] = x[b * SS + s];
        }

        // ---- GEMM: [128 x 32] += h[128 x 1024] @ Wslice[1024 x 32] ----
        wmma::fragment<wmma::accumulator, 16, 16, 16, float> acc[2];
        wmma::fill_fragment(acc[0], 0.0f);
        wmma::fill_fragment(acc[1], 0.0f);
        const int r0 = w * 16;
#pragma unroll 4
        for (int kt = 0; kt < HH; kt += 16) {
            wmma::fragment<wmma::matrix_a, 16, 16, 16, __nv_bfloat16, wmma::row_major> af;
            wmma::load_matrix_sync(af, g_h + r0 * HH + kt, HH);
#pragma unroll
            for (int nb = 0; nb < 2; nb++) {
                wmma::fragment<wmma::matrix_b, 16, 16, 16, __nv_bfloat16, wmma::col_major> bfg;
                wmma::load_matrix_sync(bfg, Ws + (nb * 16) * 1024 + kt, 1024);
                wmma::mma_sync(acc[nb], af, bfg, acc[nb]);
            }
        }
        wmma::store_matrix_sync(Sg + r0 * 32 + 0,  acc[0], 32, wmma::mem_row_major);
        wmma::store_matrix_sync(Sg + r0 * 32 + 16, acc[1], 32, wmma::mem_row_major);
        __syncthreads();

        // ---- gates + state update (fp32) ----
#pragma unroll
        for (int i = 0; i < 4; i++) {
            int e = t + i * 256; int b = e >> 3, j = e & 7;
            int u = u0 + j;
            float f  = sigm(pf[i][0] + Sg[b * 32 +      j]);
            float ii = sigm(pf[i][1] + Sg[b * 32 +  8 + j]);
            float gg = sigm(pf[i][2] + Sg[b * 32 + 16 + j]);   // sigmoid per reference
            float oo = sigm(pf[i][3] + Sg[b * 32 + 24 + j]);
            float r  = (xr[i] > 0) ? 1.0f : 0.0f;
            float C  = (gg * ii + Cs[b * 8 + j] * f) * r;
            Cs[b * 8 + j] = C;
            float h = oo * tanhf(C);
            g_h[b * HH + u] = __float2bfloat16(h);
            if (s == SS - 1) g_hf[b * HH + u] = h;
        }

        if (s < SS - 1) gridbar();   // publish h for next step
    }
}

// ======================================================================
// Kernel 3: logits = h @ Wph + bp, then row-wise log_softmax.  One CTA per batch row.
// ======================================================================
__global__ __launch_bounds__(128) void k_final(
    const float* __restrict__ Wph, const float* __restrict__ bp,
    float* __restrict__ out)
{
    __shared__ float h[HH];
    __shared__ float red[NCC];
    const int b = blockIdx.x, t = threadIdx.x;

    for (int i = t; i < HH; i += 128) h[i] = g_hf[b * HH + i];
    __syncthreads();

    float p = bp[t];
#pragma unroll 8
    for (int k = 0; k < HH; k++) p += h[k] * Wph[(size_t)k * NCC + t];

    // stable log_softmax over the 128 threads of this row
    red[t] = p; __syncthreads();
    for (int off = 64; off; off >>= 1) {
        if (t < off) red[t] = fmaxf(red[t], red[t + off]);
        __syncthreads();
    }
    float m = red[0]; __syncthreads();
    red[t] = expf(p - m); __syncthreads();
    for (int off = 64; off; off >>= 1) {
        if (t < off) red[t] += red[t + off];
        __syncthreads();
    }
    float lse = m + logf(red[0]);
    out[b * NCC + t] = p - lse;
}

// ======================================================================
extern "C" void kernel_launch(void* const* d_in, const int* in_sizes, int n_in,
                              void* d_out, int out_size)
{
    const int*   x   = (const int*)  d_in[0];
    const float* emb = (const float*)d_in[1];
    const float* Wfx = (const float*)d_in[2];
    const float* Wfh = (const float*)d_in[3];
    const float* bf  = (const float*)d_in[4];
    const float* Wix = (const float*)d_in[5];
    const float* Wih = (const float*)d_in[6];
    const float* bi  = (const float*)d_in[7];
    const float* Wgx = (const float*)d_in[8];
    const float* Wgh = (const float*)d_in[9];
    const float* bg  = (const float*)d_in[10];
    const float* Wox = (const float*)d_in[11];
    const float* Woh = (const float*)d_in[12];
    const float* bo  = (const float*)d_in[13];
    const float* Wph = (const float*)d_in[14];
    const float* bp  = (const float*)d_in[15];
    float* out = (float*)d_out;

    // 1) input-side projections
    dim3 g1(4096 / 64, (SS * BB) / 128);
    k_input_proj<<<g1, 256>>>(x, emb, Wfx, bf, Wix, bi, Wgx, bg, Wox, bo);

    // 2) persistent recurrent scan
    const int dyn_smem = 32 * 1024 * 2 + 128 * 32 * 4 + 128 * 8 * 4;  // 86016 B
    static bool attr_set = false;
    if (!attr_set) {
        cudaFuncSetAttribute(k_recur, cudaFuncAttributeMaxDynamicSharedMemorySize, dyn_smem);
        attr_set = true;
    }
    k_recur<<<NCTA_REC, 256, dyn_smem>>>(x, Wfh, Wih, Wgh, Woh);

    // 3) final projection + log_softmax
    k_final<<<BB, 128>>>(Wph, bp, out);
}

// round 3
// speedup vs baseline: 2.9488x; 2.9488x over previous
#include <cstdint>
#include <cuda_runtime.h>
#include <cuda_bf16.h>
#include <mma.h>

using namespace nvcuda;

#define BB 128
#define SS 256
#define DD 512
#define HH 1024
#define NCC 128
#define NCTA_REC 128

// ---------------- device scratch ----------------
__device__ float          g_P[(size_t)SS * BB * 4096];     // input-side preacts (no bias)
__device__ __nv_bfloat16  g_h2[2][BB * HH];                // double-buffered hidden state
__device__ float          g_hf[BB * HH];                   // final hidden state
__device__ unsigned       g_cnt = 0;
__device__ unsigned       g_gen = 0;
__device__ __nv_bfloat16  g_embb[(NCC + 1) * DD];          // bf16 embedding
__device__ __nv_bfloat16  g_Wxb[4][(size_t)DD * HH];       // bf16 input weights

__device__ __forceinline__ float sigm(float v) { return 1.0f / (1.0f + expf(-v)); }

__device__ __forceinline__ void cp16(unsigned int dst, const void* src) {
    asm volatile("cp.async.cg.shared.global [%0], [%1], 16;\n" :: "r"(dst), "l"(src));
}
__device__ __forceinline__ void cp_commit() { asm volatile("cp.async.commit_group;\n"); }
template <int N> __device__ __forceinline__ void cp_wait() {
    asm volatile("cp.async.wait_group %0;\n" :: "n"(N));
}

// Sense-reversing grid barrier (self-resetting, graph-replay safe)
__device__ __forceinline__ void gridbar()
{
    __syncthreads();
    if (threadIdx.x == 0) {
        __threadfence();
        volatile unsigned* gen = &g_gen;
        unsigned g0 = *gen;
        unsigned arr = atomicAdd(&g_cnt, 1u);
        if (arr == NCTA_REC - 1) {
            g_cnt = 0;
            __threadfence();
            *gen = g0 + 1u;
        } else {
            while (*gen == g0) { }
        }
    }
    __syncthreads();
    __threadfence();
}

// ======================================================================
// Kernel 0: one-time f32 -> bf16 conversion of emb and the 4 input weights
// ======================================================================
__global__ __launch_bounds__(256) void k_convert(
    const float* __restrict__ emb,
    const float* __restrict__ W0, const float* __restrict__ W1,
    const float* __restrict__ W2, const float* __restrict__ W3)
{
    const float* Wsrc[4] = { W0, W1, W2, W3 };
    size_t tid    = (size_t)blockIdx.x * blockDim.x + threadIdx.x;
    size_t stride = (size_t)gridDim.x * blockDim.x;
    const size_t nW4 = (size_t)DD * HH / 4;                // float4 count per matrix
    for (size_t e = tid; e < 4 * nW4; e += stride) {
        int g = (int)(e / nW4);
        size_t o = (e % nW4) * 4;
        float4 v = *(const float4*)(Wsrc[g] + o);
        __nv_bfloat16* d = &g_Wxb[g][o];
        d[0] = __float2bfloat16(v.x); d[1] = __float2bfloat16(v.y);
        d[2] = __float2bfloat16(v.z); d[3] = __float2bfloat16(v.w);
    }
    const size_t nE4 = (size_t)(NCC + 1) * DD / 4;
    for (size_t e = tid; e < nE4; e += stride) {
        float4 v = *(const float4*)(emb + e * 4);
        __nv_bfloat16* d = &g_embb[e * 4];
        d[0] = __float2bfloat16(v.x); d[1] = __float2bfloat16(v.y);
        d[2] = __float2bfloat16(v.z); d[3] = __float2bfloat16(v.w);
    }
}

// ======================================================================
// Kernel 1: input projections. C[32768,4096] = gather(embb, x) @ Wxb (bf16)
// 128x128 output tile, K-chunk 32, cp.async double-buffered, direct wmma store.
// Bias is folded into k_recur instead.
// ======================================================================
#define AS_LD 56    // padded A stride (elems): conflict-free, 16B-aligned rows
#define BS_LD 152   // padded B stride (elems)

__global__ __launch_bounds__(256) void k_input_proj(const int* __restrict__ x)
{
    __shared__ __align__(16) __nv_bfloat16 As[2][128 * AS_LD];
    __shared__ __align__(16) __nv_bfloat16 Bs[2][32 * BS_LD];
    __shared__ int rowidx[128];

    const int t = threadIdx.x, w = t >> 5;
    const int tn = blockIdx.x, tm = blockIdx.y;
    const int n0 = tn * 128, gate = n0 >> 10, h0 = n0 & 1023;
    const __nv_bfloat16* Wb = g_Wxb[gate];

    if (t < 128) {
        int m = tm * 128 + t;
        int s = m >> 7, b = m & 127;
        rowidx[t] = x[b * SS + s];
    }
    __syncthreads();

    auto issue = [&](int it) {
        int kt = it * 32;
        unsigned int Aa = (unsigned int)__cvta_generic_to_shared(As[it & 1]);
        unsigned int Ba = (unsigned int)__cvta_generic_to_shared(Bs[it & 1]);
#pragma unroll
        for (int i = 0; i < 2; i++) {                 // A: 128 rows x 32 cols
            int e = t + i * 256, r = e >> 2, seg = e & 3;
            cp16(Aa + (r * AS_LD + seg * 8) * 2,
                 g_embb + (size_t)rowidx[r] * DD + kt + seg * 8);
        }
#pragma unroll
        for (int i = 0; i < 2; i++) {                 // B: 32 rows x 128 cols
            int e = t + i * 256, r = e >> 4, seg = e & 15;
            cp16(Ba + (r * BS_LD + seg * 8) * 2,
                 Wb + (size_t)(kt + r) * HH + h0 + seg * 8);
        }
    };

    wmma::fragment<wmma::accumulator, 16, 16, 16, float> acc[8];
#pragma unroll
    for (int i = 0; i < 8; i++) wmma::fill_fragment(acc[i], 0.0f);

    issue(0); cp_commit();
    for (int it = 0; it < 16; it++) {
        if (it < 15) issue(it + 1);
        cp_commit();                 // empty group on last iter keeps wait<1> valid
        cp_wait<1>();
        __syncthreads();
        const __nv_bfloat16* A = As[it & 1];
        const __nv_bfloat16* B = Bs[it & 1];
#pragma unroll
        for (int ks = 0; ks < 2; ks++) {
            wmma::fragment<wmma::matrix_a, 16, 16, 16, __nv_bfloat16, wmma::row_major> af;
            wmma::load_matrix_sync(af, A + (w * 16) * AS_LD + ks * 16, AS_LD);
#pragma unroll
            for (int nb = 0; nb < 8; nb++) {
                wmma::fragment<wmma::matrix_b, 16, 16, 16, __nv_bfloat16, wmma::row_major> bfr;
                wmma::load_matrix_sync(bfr, B + (ks * 16) * BS_LD + nb * 16, BS_LD);
                wmma::mma_sync(acc[nb], af, bfr, acc[nb]);
            }
        }
        __syncthreads();
    }

    size_t base = (size_t)(tm * 128 + w * 16) * 4096 + n0;
#pragma unroll
    for (int nb = 0; nb < 8; nb++)
        wmma::store_matrix_sync(g_P + base + nb * 16, acc[nb], 4096, wmma::mem_row_major);
}

// ======================================================================
// Kernel 2: persistent recurrent scan. 128 CTAs x 8 hidden units.
// h staged in SMEM via cp.async (double-buffered 128-col chunks); weights in
// SMEM for all steps; h globally double-buffered (race-free).
// ======================================================================
#define WS_LD 1032  // padded weight stride (elems)
#define HA_LD 152   // padded h-tile stride (elems)

__global__ void __launch_bounds__(256, 1) k_recur(
    const int*   __restrict__ x,
    const float* __restrict__ Wfh, const float* __restrict__ Wih,
    const float* __restrict__ Wgh, const float* __restrict__ Woh,
    const float* __restrict__ bfp, const float* __restrict__ bip,
    const float* __restrict__ bgp, const float* __restrict__ bop)
{
    extern __shared__ __align__(16) unsigned char dyn[];
    __nv_bfloat16* Ws  = (__nv_bfloat16*)dyn;              // [32][WS_LD] col-major
    __nv_bfloat16* hAb[2];
    hAb[0] = Ws + 32 * WS_LD;
    hAb[1] = hAb[0] + 128 * HA_LD;
    float* Sg = (float*)(hAb[1] + 128 * HA_LD);            // [128][32]
    float* Cs = Sg + 128 * 32;                             // [128][8]

    const int t = threadIdx.x, w = t >> 5;
    const int c = blockIdx.x, u0 = c * 8;
    const float* Wg[4] = { Wfh, Wih, Wgh, Woh };

    // weight slice -> SMEM (bf16, col-major, padded stride)
    for (int e = t; e < 32 * 1024; e += 256) {
        int k = e >> 5, col = e & 31, g = col >> 3, j = col & 7;
        Ws[col * WS_LD + k] = __float2bfloat16(Wg[g][(size_t)k * HH + u0 + j]);
    }
    // zero own h slice (read buffer for s=0) and C
    for (int e = t; e < 1024; e += 256) {
        int b = e >> 3, j = e & 7;
        g_h2[0][b * HH + u0 + j] = __float2bfloat16(0.0f);
        Cs[b * 8 + j] = 0.0f;
    }
    const int jj = t & 7;
    const float bias0 = bfp[u0 + jj], bias1 = bip[u0 + jj];
    const float bias2 = bgp[u0 + jj], bias3 = bop[u0 + jj];

    unsigned int hAa[2] = { (unsigned int)__cvta_generic_to_shared(hAb[0]),
                            (unsigned int)__cvta_generic_to_shared(hAb[1]) };

    gridbar();   // zeros visible everywhere

    for (int s = 0; s < SS; s++) {
        const __nv_bfloat16* hsrc = g_h2[s & 1];
        __nv_bfloat16*       hdst = g_h2[(s + 1) & 1];

        // prefetch input-side preacts + reset mask (independent of h)
        float pf[4][4]; int xr[4];
#pragma unroll
        for (int i = 0; i < 4; i++) {
            int e = t + i * 256, b = e >> 3, j = e & 7;
            const float* Pb = g_P + ((size_t)(s * BB + b)) * 4096 + (u0 + j);
            pf[i][0] = Pb[0];    pf[i][1] = Pb[1024];
            pf[i][2] = Pb[2048]; pf[i][3] = Pb[3072];
            xr[i] = x[b * SS + s];
        }

        // issue chunk 0
#pragma unroll
        for (int i = 0; i < 8; i++) {
            int e = t + i * 256, r = e >> 4, seg = e & 15;
            cp16(hAa[0] + (r * HA_LD + seg * 8) * 2, hsrc + r * HH + seg * 8);
        }
        cp_commit();

        wmma::fragment<wmma::accumulator, 16, 16, 16, float> acc[2];
        wmma::fill_fragment(acc[0], 0.0f);
        wmma::fill_fragment(acc[1], 0.0f);

        for (int kc = 0; kc < 8; kc++) {
            if (kc < 7) {
#pragma unroll
                for (int i = 0; i < 8; i++) {
                    int e = t + i * 256, r = e >> 4, seg = e & 15;
                    cp16(hAa[(kc + 1) & 1] + (r * HA_LD + seg * 8) * 2,
                         hsrc + r * HH + (kc + 1) * 128 + seg * 8);
                }
            }
            cp_commit();
            cp_wait<1>();
            __syncthreads();
            const __nv_bfloat16* A = hAb[kc & 1];
#pragma unroll
            for (int ks = 0; ks < 8; ks++) {
                wmma::fragment<wmma::matrix_a, 16, 16, 16, __nv_bfloat16, wmma::row_major> af;
                wmma::load_matrix_sync(af, A + (w * 16) * HA_LD + ks * 16, HA_LD);
#pragma unroll
                for (int nb = 0; nb < 2; nb++) {
                    wmma::fragment<wmma::matrix_b, 16, 16, 16, __nv_bfloat16, wmma::col_major> bfr;
                    wmma::load_matrix_sync(bfr, Ws + (nb * 16) * WS_LD + kc * 128 + ks * 16, WS_LD);
                    wmma::mma_sync(acc[nb], af, bfr, acc[nb]);
                }
            }
            __syncthreads();
        }

        wmma::store_matrix_sync(Sg + (w * 16) * 32 + 0,  acc[0], 32, wmma::mem_row_major);
        wmma::store_matrix_sync(Sg + (w * 16) * 32 + 16, acc[1], 32, wmma::mem_row_major);
        __syncthreads();

#pragma unroll
        for (int i = 0; i < 4; i++) {
            int e = t + i * 256, b = e >> 3, j = e & 7, u = u0 + j;
            float f  = sigm(pf[i][0] + bias0 + Sg[b * 32 +      j]);
            float ii = sigm(pf[i][1] + bias1 + Sg[b * 32 +  8 + j]);
            float gg = sigm(pf[i][2] + bias2 + Sg[b * 32 + 16 + j]);
            float oo = sigm(pf[i][3] + bias3 + Sg[b * 32 + 24 + j]);
            float r  = (xr[i] > 0) ? 1.0f : 0.0f;
            float C  = (gg * ii + Cs[b * 8 + j] * f) * r;
            Cs[b * 8 + j] = C;
            float h = oo * tanhf(C);
            hdst[b * HH + u] = __float2bfloat16(h);
            if (s == SS - 1) g_hf[b * HH + u] = h;
        }

        if (s < SS - 1) gridbar();
    }
}

// ======================================================================
// Kernel 3: logits + log_softmax
// ======================================================================
__global__ __launch_bounds__(128) void k_final(
    const float* __restrict__ Wph, const float* __restrict__ bp,
    float* __restrict__ out)
{
    __shared__ float h[HH];
    __shared__ float red[NCC];
    const int b = blockIdx.x, t = threadIdx.x;

    for (int i = t; i < HH; i += 128) h[i] = g_hf[b * HH + i];
    __syncthreads();

    float p = bp[t];
#pragma unroll 8
    for (int k = 0; k < HH; k++) p += h[k] * Wph[(size_t)k * NCC + t];

    red[t] = p; __syncthreads();
    for (int off = 64; off; off >>= 1) {
        if (t < off) red[t] = fmaxf(red[t], red[t + off]);
        __syncthreads();
    }
    float m = red[0]; __syncthreads();
    red[t] = expf(p - m); __syncthreads();
    for (int off = 64; off; off >>= 1) {
        if (t < off) red[t] += red[t + off];
        __syncthreads();
    }
    float lse = m + logf(red[0]);
    out[b * NCC + t] = p - lse;
}

// ======================================================================
extern "C" void kernel_launch(void* const* d_in, const int* in_sizes, int n_in,
                              void* d_out, int out_size)
{
    const int*   x   = (const int*)  d_in[0];
    const float* emb = (const float*)d_in[1];
    const float* Wfx = (const float*)d_in[2];
    const float* Wfh = (const float*)d_in[3];
    const float* bf  = (const float*)d_in[4];
    const float* Wix = (const float*)d_in[5];
    const float* Wih = (const float*)d_in[6];
    const float* bi  = (const float*)d_in[7];
    const float* Wgx = (const float*)d_in[8];
    const float* Wgh = (const float*)d_in[9];
    const float* bg  = (const float*)d_in[10];
    const float* Wox = (const float*)d_in[11];
    const float* Woh = (const float*)d_in[12];
    const float* bo  = (const float*)d_in[13];
    const float* Wph = (const float*)d_in[14];
    const float* bp  = (const float*)d_in[15];
    float* out = (float*)d_out;

    // 0) bf16 pre-conversion (emb + input weights)
    k_convert<<<512, 256>>>(emb, Wfx, Wix, Wgx, Wox);

    // 1) input-side projections
    dim3 g1(4096 / 128, (SS * BB) / 128);
    k_input_proj<<<g1, 256>>>(x);

    // 2) persistent recurrent scan
    const int dyn_smem = 32 * WS_LD * 2 + 2 * 128 * HA_LD * 2 + 128 * 32 * 4 + 128 * 8 * 4;
    static bool attr_set = false;
    if (!attr_set) {
        cudaFuncSetAttribute(k_recur, cudaFuncAttributeMaxDynamicSharedMemorySize, dyn_smem);
        attr_set = true;
    }
    k_recur<<<NCTA_REC, 256, dyn_smem>>>(x, Wfh, Wih, Wgh, Woh, bf, bi, bg, bo);

    // 3) final projection + log_softmax
    k_final<<<BB, 128>>>(Wph, bp, out);
}